// round 1
// baseline (speedup 1.0000x reference)
#include <cuda_runtime.h>

#define S 160
#define SS (S*S)
#define S3 (S*S*S)
#define DG 96
#define DG2 (DG*DG)
#define DG3 (DG*DG*DG)
#define IMG_H 240
#define IMG_W 320
#define NVIEW 3
#define NPIX (NVIEW*IMG_H*IMG_W)   // 230400
#define TPB 256
#define NBLK (NPIX/TPB)            // 900
#define NSTEP 64
#define CLAMP_HI 158.999f          // f32(160 - 1.001)

__device__ float g_sdf[S3];        // resized SDF minus TRUNC, 16.4 MB
__device__ float g_psum[NBLK];
__device__ int   g_pcnt[NBLK];

// ---------------------------------------------------------------------------
// Kernel 1: trilinear resize 96^3 -> 160^3, subtract TRUNC=1.5
// ---------------------------------------------------------------------------
__global__ void resize_sdf_kernel(const float* __restrict__ sdf) {
    int t = blockIdx.x * TPB + threadIdx.x;       // exactly S3 threads
    int k = t % S;
    int j = (t / S) % S;
    int i = t / SS;

    float cx = (i * 95.0f) / 159.0f;
    float cy = (j * 95.0f) / 159.0f;
    float cz = (k * 95.0f) / 159.0f;
    int x0 = (int)cx, y0 = (int)cy, z0 = (int)cz;
    float fx = cx - (float)x0, fy = cy - (float)y0, fz = cz - (float)z0;
    int x1 = min(x0 + 1, DG - 1), y1 = min(y0 + 1, DG - 1), z1 = min(z0 + 1, DG - 1);

    int i000 = (x0 * DG + y0) * DG + z0;
    int xs = (x1 - x0) * DG2;
    int ys = (y1 - y0) * DG;
    int zs = (z1 - z0);

    float v000 = __ldg(sdf + i000);
    float v100 = __ldg(sdf + i000 + xs);
    float v010 = __ldg(sdf + i000 + ys);
    float v001 = __ldg(sdf + i000 + zs);
    float v110 = __ldg(sdf + i000 + xs + ys);
    float v101 = __ldg(sdf + i000 + xs + zs);
    float v011 = __ldg(sdf + i000 + ys + zs);
    float v111 = __ldg(sdf + i000 + xs + ys + zs);

    float gx = 1.0f - fx, gy = 1.0f - fy, gz = 1.0f - fz;
    float r = v000 * gx * gy * gz
            + v100 * fx * gy * gz
            + v010 * gx * fy * gz
            + v001 * gx * gy * fz
            + v110 * fx * fy * gz
            + v101 * fx * gy * fz
            + v011 * gx * fy * fz
            + v111 * fx * fy * fz;

    g_sdf[t] = r - 1.5f;
}

// ---------------------------------------------------------------------------
// SDF trilerp on the materialized 160^3 grid (matches reference _trilerp)
// ---------------------------------------------------------------------------
__device__ __forceinline__ float sdf_sample(float px, float py, float pz) {
    float cx = fminf(fmaxf(px, 0.0f), CLAMP_HI);
    float cy = fminf(fmaxf(py, 0.0f), CLAMP_HI);
    float cz = fminf(fmaxf(pz, 0.0f), CLAMP_HI);
    int x0 = (int)cx, y0 = (int)cy, z0 = (int)cz;
    float fx = cx - (float)x0, fy = cy - (float)y0, fz = cz - (float)z0;
    int x1 = min(x0 + 1, S - 1), y1 = min(y0 + 1, S - 1), z1 = min(z0 + 1, S - 1);

    int i000 = (x0 * S + y0) * S + z0;
    int xs = (x1 - x0) * SS;
    int ys = (y1 - y0) * S;
    int zs = (z1 - z0);

    float v000 = g_sdf[i000];
    float v100 = g_sdf[i000 + xs];
    float v010 = g_sdf[i000 + ys];
    float v001 = g_sdf[i000 + zs];
    float v110 = g_sdf[i000 + xs + ys];
    float v101 = g_sdf[i000 + xs + zs];
    float v011 = g_sdf[i000 + ys + zs];
    float v111 = g_sdf[i000 + xs + ys + zs];

    float gx = 1.0f - fx, gy = 1.0f - fy, gz = 1.0f - fz;
    return v000 * gx * gy * gz
         + v100 * fx * gy * gz
         + v010 * gx * fy * gz
         + v001 * gx * gy * fz
         + v110 * fx * fy * gz
         + v101 * fx * gy * fz
         + v011 * gx * fy * fz
         + v111 * fx * fy * fz;
}

// ---------------------------------------------------------------------------
// On-the-fly resized RGB(trilinear) + sem(NN) value at integer resized coords
// Identical math to materializing the resized volumes, so it is exact.
// ---------------------------------------------------------------------------
__device__ __forceinline__ void resized_rgbsem(const float* __restrict__ rgb,
                                               const float* __restrict__ sem,
                                               int i, int j, int k, float out[4]) {
    float cx = (i * 95.0f) / 159.0f;
    float cy = (j * 95.0f) / 159.0f;
    float cz = (k * 95.0f) / 159.0f;
    int x0 = (int)cx, y0 = (int)cy, z0 = (int)cz;
    float fx = cx - (float)x0, fy = cy - (float)y0, fz = cz - (float)z0;
    int x1 = min(x0 + 1, DG - 1), y1 = min(y0 + 1, DG - 1), z1 = min(z0 + 1, DG - 1);

    int i000 = (x0 * DG + y0) * DG + z0;
    int xs = (x1 - x0) * DG2;
    int ys = (y1 - y0) * DG;
    int zs = (z1 - z0);

    float gx = 1.0f - fx, gy = 1.0f - fy, gz = 1.0f - fz;
    float w000 = gx * gy * gz, w100 = fx * gy * gz;
    float w010 = gx * fy * gz, w001 = gx * gy * fz;
    float w110 = fx * fy * gz, w101 = fx * gy * fz;
    float w011 = gx * fy * fz, w111 = fx * fy * fz;

#pragma unroll
    for (int c = 0; c < 3; c++) {
        const float* b = rgb + c * DG3;
        out[c] = __ldg(b + i000) * w000
               + __ldg(b + i000 + xs) * w100
               + __ldg(b + i000 + ys) * w010
               + __ldg(b + i000 + zs) * w001
               + __ldg(b + i000 + xs + ys) * w110
               + __ldg(b + i000 + xs + zs) * w101
               + __ldg(b + i000 + ys + zs) * w011
               + __ldg(b + i000 + xs + ys + zs) * w111;
    }
    // nearest-neighbor resize index: floor(i * 96/160)
    int xi = min((int)(i * 0.6f), DG - 1);
    int yi = min((int)(j * 0.6f), DG - 1);
    int zi = min((int)(k * 0.6f), DG - 1);
    out[3] = __ldg(sem + (xi * DG + yi) * DG + zi);
}

// ---------------------------------------------------------------------------
// Kernel 2: ray march + final sample + loss contribution, block-partials
// ---------------------------------------------------------------------------
__global__ void march_kernel(const float* __restrict__ rgb,
                             const float* __restrict__ sem,
                             const float* __restrict__ poses,
                             const float* __restrict__ views) {
    int tid = blockIdx.x * TPB + threadIdx.x;     // exactly NPIX threads
    int v = tid / (IMG_H * IMG_W);
    int r = tid % (IMG_H * IMG_W);
    int h = r / IMG_W;
    int w = r % IMG_W;

    const float offx[3] = {0.0f, 36.0f, 40.0f};
    const float offz[3] = {0.0f, 44.0f, 23.0f};

    const float* M = poses + v * 16;
    float ox = M[3]  / 0.0301f + offx[v];
    float oy = M[7]  / 0.0301f;                   // OFFSETS y == 0 for all views
    float oz = M[11] / 0.0301f + offz[v];

    float uu = ((float)w - 160.0f) / 277.0f;
    float vv = ((float)h - 120.0f) / 277.0f;

    float dx = M[0] * uu + M[1] * vv + M[2];
    float dy = M[4] * uu + M[5] * vv + M[6];
    float dz = M[8] * uu + M[9] * vv + M[10];
    float nrm = sqrtf(dx * dx + dy * dy + dz * dz);
    dx /= nrm; dy /= nrm; dz /= nrm;

    float t = 0.0f;
#pragma unroll 1
    for (int it = 0; it < NSTEP; ++it) {
        float px = ox + t * dx;
        float py = oy + t * dy;
        float pz = oz + t * dz;
        float s = sdf_sample(px, py, pz);
        t += fmaxf(s, 0.25f) * 2.0f;
    }

    // final sample (shares corner/weight computation between sdf and rgb outer lerp)
    float px = ox + t * dx;
    float py = oy + t * dy;
    float pz = oz + t * dz;

    float cx = fminf(fmaxf(px, 0.0f), CLAMP_HI);
    float cy = fminf(fmaxf(py, 0.0f), CLAMP_HI);
    float cz = fminf(fmaxf(pz, 0.0f), CLAMP_HI);
    int x0 = (int)cx, y0 = (int)cy, z0 = (int)cz;
    float fx = cx - (float)x0, fy = cy - (float)y0, fz = cz - (float)z0;
    int x1 = min(x0 + 1, S - 1), y1 = min(y0 + 1, S - 1), z1 = min(z0 + 1, S - 1);

    int i000 = (x0 * S + y0) * S + z0;
    int xs = (x1 - x0) * SS;
    int ys = (y1 - y0) * S;
    int zs = (z1 - z0);

    float gx = 1.0f - fx, gy = 1.0f - fy, gz = 1.0f - fz;
    float w000 = gx * gy * gz, w100 = fx * gy * gz;
    float w010 = gx * fy * gz, w001 = gx * gy * fz;
    float w110 = fx * fy * gz, w101 = fx * gy * fz;
    float w011 = gx * fy * fz, w111 = fx * fy * fz;

    float s = g_sdf[i000] * w000
            + g_sdf[i000 + xs] * w100
            + g_sdf[i000 + ys] * w010
            + g_sdf[i000 + zs] * w001
            + g_sdf[i000 + xs + ys] * w110
            + g_sdf[i000 + xs + zs] * w101
            + g_sdf[i000 + ys + zs] * w011
            + g_sdf[i000 + xs + ys + zs] * w111;

    bool inside = (px >= 0.0f) && (px <= 159.0f)
               && (py >= 0.0f) && (py <= 159.0f)
               && (pz >= 0.0f) && (pz <= 159.0f);
    bool valid = inside && (fabsf(s) < 1.0f);

    float contrib = 0.0f;
    int cnt = 0;
    if (valid) {
        float acc0 = 0.f, acc1 = 0.f, acc2 = 0.f, acc3 = 0.f;
        float c4[4];
        resized_rgbsem(rgb, sem, x0, y0, z0, c4);
        acc0 += w000 * c4[0]; acc1 += w000 * c4[1]; acc2 += w000 * c4[2]; acc3 += w000 * c4[3];
        resized_rgbsem(rgb, sem, x1, y0, z0, c4);
        acc0 += w100 * c4[0]; acc1 += w100 * c4[1]; acc2 += w100 * c4[2]; acc3 += w100 * c4[3];
        resized_rgbsem(rgb, sem, x0, y1, z0, c4);
        acc0 += w010 * c4[0]; acc1 += w010 * c4[1]; acc2 += w010 * c4[2]; acc3 += w010 * c4[3];
        resized_rgbsem(rgb, sem, x0, y0, z1, c4);
        acc0 += w001 * c4[0]; acc1 += w001 * c4[1]; acc2 += w001 * c4[2]; acc3 += w001 * c4[3];
        resized_rgbsem(rgb, sem, x1, y1, z0, c4);
        acc0 += w110 * c4[0]; acc1 += w110 * c4[1]; acc2 += w110 * c4[2]; acc3 += w110 * c4[3];
        resized_rgbsem(rgb, sem, x1, y0, z1, c4);
        acc0 += w101 * c4[0]; acc1 += w101 * c4[1]; acc2 += w101 * c4[2]; acc3 += w101 * c4[3];
        resized_rgbsem(rgb, sem, x0, y1, z1, c4);
        acc0 += w011 * c4[0]; acc1 += w011 * c4[1]; acc2 += w011 * c4[2]; acc3 += w011 * c4[3];
        resized_rgbsem(rgb, sem, x1, y1, z1, c4);
        acc0 += w111 * c4[0]; acc1 += w111 * c4[1]; acc2 += w111 * c4[2]; acc3 += w111 * c4[3];

        const float* vw = views + ((size_t)(v * IMG_H + h) * IMG_W + w) * 3;
        contrib = (fabsf(acc0 - vw[0]) + fabsf(acc1 - vw[1]) + fabsf(acc2 - vw[2])) * acc3;
        cnt = 1;
    }

    // deterministic block reduction
    __shared__ float ssum[TPB];
    __shared__ int scnt[TPB];
    int tx = threadIdx.x;
    ssum[tx] = contrib;
    scnt[tx] = cnt;
    __syncthreads();
#pragma unroll
    for (int o = TPB / 2; o > 0; o >>= 1) {
        if (tx < o) {
            ssum[tx] += ssum[tx + o];
            scnt[tx] += scnt[tx + o];
        }
        __syncthreads();
    }
    if (tx == 0) {
        g_psum[blockIdx.x] = ssum[0];
        g_pcnt[blockIdx.x] = scnt[0];
    }
}

// ---------------------------------------------------------------------------
// Kernel 3: final deterministic reduction + loss
// ---------------------------------------------------------------------------
__global__ void finish_kernel(float* __restrict__ out) {
    __shared__ float ss[1024];
    __shared__ int sc[1024];
    int t = threadIdx.x;
    ss[t] = (t < NBLK) ? g_psum[t] : 0.0f;
    sc[t] = (t < NBLK) ? g_pcnt[t] : 0;
    __syncthreads();
#pragma unroll
    for (int o = 512; o > 0; o >>= 1) {
        if (t < o) {
            ss[t] += ss[t + o];
            sc[t] += sc[t + o];
        }
        __syncthreads();
    }
    if (t == 0) {
        float nv = 3.0f * (float)sc[0];   // mask broadcast over 3 channels
        out[0] = 8.0f * ss[0] / fmaxf(nv, 1.0f);
    }
}

// ---------------------------------------------------------------------------
extern "C" void kernel_launch(void* const* d_in, const int* in_sizes, int n_in,
                              void* d_out, int out_size) {
    const float* sdf   = (const float*)d_in[0];
    const float* rgb   = (const float*)d_in[1];
    const float* sem   = (const float*)d_in[2];
    const float* poses = (const float*)d_in[3];
    const float* views = (const float*)d_in[4];

    resize_sdf_kernel<<<S3 / TPB, TPB>>>(sdf);
    march_kernel<<<NBLK, TPB>>>(rgb, sem, poses, views);
    finish_kernel<<<1, 1024>>>((float*)d_out);
}

// round 2
// speedup vs baseline: 1.2048x; 1.2048x over previous
#include <cuda_runtime.h>

#define S 160
#define SS (S*S)
#define S3 (S*S*S)
#define DG 96
#define DG2 (DG*DG)
#define DG3 (DG*DG*DG)
#define IMG_H 240
#define IMG_W 320
#define NVIEW 3
#define NPIX (NVIEW*IMG_H*IMG_W)   // 230400
#define NSTEP 64
#define CLAMP_HI 158.999f          // f32(160 - 1.001)
#define NBLK 900                   // march blocks (10 x 30 x 3)

// packed resized volumes
__device__ float2 g_sdf2[S3];      // (sdf[z], sdf[z+1]) - TRUNC, 32 MB
__device__ float4 g_rgbw[S3];      // (r, g, b, sem_nn), 64 MB
__device__ float  g_psum[NBLK];
__device__ int    g_pcnt[NBLK];

// ---------------------------------------------------------------------------
// Kernel 1: separable resize of all channels. One block per output (i,j) row.
//   stage 1: 96 threads bilerp source rows (x,y fixed) into smem lines
//   stage 2: 160 threads do the z-lerp, pack sdf float2 + rgbw float4
// ---------------------------------------------------------------------------
__global__ __launch_bounds__(160) void resize_all_kernel(
        const float* __restrict__ sdf,
        const float* __restrict__ rgb,
        const float* __restrict__ sem) {
    int b = blockIdx.x;            // 25600 = S*S
    int i = b / S, j = b % S;
    int t = threadIdx.x;           // 160

    float cx = (i * 95.0f) / 159.0f;
    int x0 = (int)cx; float fx = cx - (float)x0; int x1 = min(x0 + 1, DG - 1);
    float cy = (j * 95.0f) / 159.0f;
    int y0 = (int)cy; float fy = cy - (float)y0; int y1 = min(y0 + 1, DG - 1);

    __shared__ float ls[96], lr[96], lg[96], lb[96];
    __shared__ float rowS[161];

    if (t < 96) {
        int base = (x0 * DG + y0) * DG + t;
        int xs = (x1 - x0) * DG2;
        int ys = (y1 - y0) * DG;
        float gxf = 1.0f - fx, gyf = 1.0f - fy;
        float w00 = gxf * gyf, w01 = gxf * fy, w10 = fx * gyf, w11 = fx * fy;

        ls[t] = __ldg(sdf + base) * w00 + __ldg(sdf + base + ys) * w01
              + __ldg(sdf + base + xs) * w10 + __ldg(sdf + base + xs + ys) * w11;
        const float* r = rgb;
        lr[t] = __ldg(r + base) * w00 + __ldg(r + base + ys) * w01
              + __ldg(r + base + xs) * w10 + __ldg(r + base + xs + ys) * w11;
        const float* g = rgb + DG3;
        lg[t] = __ldg(g + base) * w00 + __ldg(g + base + ys) * w01
              + __ldg(g + base + xs) * w10 + __ldg(g + base + xs + ys) * w11;
        const float* bl = rgb + 2 * DG3;
        lb[t] = __ldg(bl + base) * w00 + __ldg(bl + base + ys) * w01
              + __ldg(bl + base + xs) * w10 + __ldg(bl + base + xs + ys) * w11;
    }
    if (t == 0) rowS[160] = 0.0f;
    __syncthreads();

    float czf = (t * 95.0f) / 159.0f;
    int z0 = (int)czf; float fz = czf - (float)z0; int z1 = min(z0 + 1, DG - 1);

    float sv = fmaf(fz, ls[z1] - ls[z0], ls[z0]) - 1.5f;
    float rv = fmaf(fz, lr[z1] - lr[z0], lr[z0]);
    float gv = fmaf(fz, lg[z1] - lg[z0], lg[z0]);
    float bv = fmaf(fz, lb[z1] - lb[z0], lb[z0]);

    int xi = min((int)(i * 0.6f), DG - 1);
    int yi = min((int)(j * 0.6f), DG - 1);
    int zi = min((int)(t * 0.6f), DG - 1);
    float wv = __ldg(sem + (xi * DG + yi) * DG + zi);

    rowS[t] = sv;
    int o = (i * S + j) * S + t;
    g_rgbw[o] = make_float4(rv, gv, bv, wv);
    __syncthreads();
    g_sdf2[o] = make_float2(rowS[t], rowS[t + 1]);
}

// ---------------------------------------------------------------------------
// SDF sample: 4 float2 loads (z-pairs), nested lerp
// ---------------------------------------------------------------------------
__device__ __forceinline__ float sdf_sample2(float px, float py, float pz) {
    float cx = fminf(fmaxf(px, 0.0f), CLAMP_HI);
    float cy = fminf(fmaxf(py, 0.0f), CLAMP_HI);
    float cz = fminf(fmaxf(pz, 0.0f), CLAMP_HI);
    int x0 = (int)cx, y0 = (int)cy, z0 = (int)cz;
    float fx = cx - (float)x0, fy = cy - (float)y0, fz = cz - (float)z0;

    const float2* p = g_sdf2 + ((x0 * S + y0) * S + z0);
    float2 a00 = __ldg(p);
    float2 a01 = __ldg(p + S);
    float2 a10 = __ldg(p + SS);
    float2 a11 = __ldg(p + SS + S);

    float v00 = fmaf(fz, a00.y - a00.x, a00.x);
    float v01 = fmaf(fz, a01.y - a01.x, a01.x);
    float v10 = fmaf(fz, a10.y - a10.x, a10.x);
    float v11 = fmaf(fz, a11.y - a11.x, a11.x);
    float v0 = fmaf(fy, v01 - v00, v00);
    float v1 = fmaf(fy, v11 - v10, v10);
    return fmaf(fx, v1 - v0, v0);
}

__device__ __forceinline__ float4 lerp4(float4 a, float4 b, float f) {
    return make_float4(fmaf(f, b.x - a.x, a.x), fmaf(f, b.y - a.y, a.y),
                       fmaf(f, b.z - a.z, a.z), fmaf(f, b.w - a.w, a.w));
}

// ---------------------------------------------------------------------------
// Kernel 2: ray march with 8x4 warp tiles + dead-ray predication
// grid (10, 30, 3), block 256 => block covers 32w x 8h pixels of one view
// ---------------------------------------------------------------------------
__global__ __launch_bounds__(256) void march_kernel(
        const float* __restrict__ poses,
        const float* __restrict__ views) {
    int tid = threadIdx.x;
    int warp = tid >> 5, lane = tid & 31;
    int wx = warp & 3, wy = warp >> 2;
    int lx = lane & 7, ly = lane >> 3;
    int w = blockIdx.x * 32 + wx * 8 + lx;
    int h = blockIdx.y * 8 + wy * 4 + ly;
    int v = blockIdx.z;

    const float offx[3] = {0.0f, 36.0f, 40.0f};
    const float offz[3] = {0.0f, 44.0f, 23.0f};

    const float* M = poses + v * 16;
    float ox = M[3]  / 0.0301f + offx[v];
    float oy = M[7]  / 0.0301f;
    float oz = M[11] / 0.0301f + offz[v];

    float uu = ((float)w - 160.0f) / 277.0f;
    float vv = ((float)h - 120.0f) / 277.0f;

    float dx = M[0] * uu + M[1] * vv + M[2];
    float dy = M[4] * uu + M[5] * vv + M[6];
    float dz = M[8] * uu + M[9] * vv + M[10];
    float nrm = sqrtf(dx * dx + dy * dy + dz * dz);
    dx /= nrm; dy /= nrm; dz /= nrm;

    float t = 0.0f;
    bool alive = true;
#pragma unroll 1
    for (int it = 0; it < NSTEP; ++it) {
        if (alive) {
            float px = fmaf(t, dx, ox);
            float py = fmaf(t, dy, oy);
            float pz = fmaf(t, dz, oz);
            // out-and-moving-away on any axis => final 'inside' is false forever
            bool dead = (px < 0.0f && dx <= 0.0f) || (px > 159.0f && dx >= 0.0f)
                     || (py < 0.0f && dy <= 0.0f) || (py > 159.0f && dy >= 0.0f)
                     || (pz < 0.0f && dz <= 0.0f) || (pz > 159.0f && dz >= 0.0f);
            if (dead) {
                alive = false;
            } else {
                float s = sdf_sample2(px, py, pz);
                t = fmaf(fmaxf(s, 0.25f), 2.0f, t);
            }
        }
        if (__all_sync(0xffffffffu, !alive)) break;
    }

    float contrib = 0.0f;
    int cnt = 0;
    if (alive) {
        float px = fmaf(t, dx, ox);
        float py = fmaf(t, dy, oy);
        float pz = fmaf(t, dz, oz);

        float cx = fminf(fmaxf(px, 0.0f), CLAMP_HI);
        float cy = fminf(fmaxf(py, 0.0f), CLAMP_HI);
        float cz = fminf(fmaxf(pz, 0.0f), CLAMP_HI);
        int x0 = (int)cx, y0 = (int)cy, z0 = (int)cz;
        float fx = cx - (float)x0, fy = cy - (float)y0, fz = cz - (float)z0;
        int idx = (x0 * S + y0) * S + z0;

        const float2* p = g_sdf2 + idx;
        float2 a00 = __ldg(p);
        float2 a01 = __ldg(p + S);
        float2 a10 = __ldg(p + SS);
        float2 a11 = __ldg(p + SS + S);
        float v00 = fmaf(fz, a00.y - a00.x, a00.x);
        float v01 = fmaf(fz, a01.y - a01.x, a01.x);
        float v10 = fmaf(fz, a10.y - a10.x, a10.x);
        float v11 = fmaf(fz, a11.y - a11.x, a11.x);
        float v0 = fmaf(fy, v01 - v00, v00);
        float v1 = fmaf(fy, v11 - v10, v10);
        float s = fmaf(fx, v1 - v0, v0);

        bool inside = (px >= 0.0f) && (px <= 159.0f)
                   && (py >= 0.0f) && (py <= 159.0f)
                   && (pz >= 0.0f) && (pz <= 159.0f);
        bool valid = inside && (fabsf(s) < 1.0f);

        if (valid) {
            const float4* q = g_rgbw + idx;
            float4 c000 = __ldg(q),          c001 = __ldg(q + 1);
            float4 c010 = __ldg(q + S),      c011 = __ldg(q + S + 1);
            float4 c100 = __ldg(q + SS),     c101 = __ldg(q + SS + 1);
            float4 c110 = __ldg(q + SS + S), c111 = __ldg(q + SS + S + 1);
            float4 m00 = lerp4(c000, c001, fz);
            float4 m01 = lerp4(c010, c011, fz);
            float4 m10 = lerp4(c100, c101, fz);
            float4 m11 = lerp4(c110, c111, fz);
            float4 m0 = lerp4(m00, m01, fy);
            float4 m1 = lerp4(m10, m11, fy);
            float4 col = lerp4(m0, m1, fx);

            const float* vw = views + ((size_t)(v * IMG_H + h) * IMG_W + w) * 3;
            contrib = (fabsf(col.x - vw[0]) + fabsf(col.y - vw[1])
                     + fabsf(col.z - vw[2])) * col.w;
            cnt = 1;
        }
    }

    // deterministic block reduction
    __shared__ float ssum[256];
    __shared__ int scnt[256];
    ssum[tid] = contrib;
    scnt[tid] = cnt;
    __syncthreads();
#pragma unroll
    for (int o = 128; o > 0; o >>= 1) {
        if (tid < o) {
            ssum[tid] += ssum[tid + o];
            scnt[tid] += scnt[tid + o];
        }
        __syncthreads();
    }
    if (tid == 0) {
        int bid = (blockIdx.z * gridDim.y + blockIdx.y) * gridDim.x + blockIdx.x;
        g_psum[bid] = ssum[0];
        g_pcnt[bid] = scnt[0];
    }
}

// ---------------------------------------------------------------------------
// Kernel 3: final deterministic reduction + loss
// ---------------------------------------------------------------------------
__global__ void finish_kernel(float* __restrict__ out) {
    __shared__ float ss[1024];
    __shared__ int sc[1024];
    int t = threadIdx.x;
    ss[t] = (t < NBLK) ? g_psum[t] : 0.0f;
    sc[t] = (t < NBLK) ? g_pcnt[t] : 0;
    __syncthreads();
#pragma unroll
    for (int o = 512; o > 0; o >>= 1) {
        if (t < o) {
            ss[t] += ss[t + o];
            sc[t] += sc[t + o];
        }
        __syncthreads();
    }
    if (t == 0) {
        float nv = 3.0f * (float)sc[0];
        out[0] = 8.0f * ss[0] / fmaxf(nv, 1.0f);
    }
}

// ---------------------------------------------------------------------------
extern "C" void kernel_launch(void* const* d_in, const int* in_sizes, int n_in,
                              void* d_out, int out_size) {
    const float* sdf   = (const float*)d_in[0];
    const float* rgb   = (const float*)d_in[1];
    const float* sem   = (const float*)d_in[2];
    const float* poses = (const float*)d_in[3];
    const float* views = (const float*)d_in[4];

    resize_all_kernel<<<S * S, 160>>>(sdf, rgb, sem);
    dim3 mg(IMG_W / 32, IMG_H / 8, NVIEW);
    march_kernel<<<mg, 256>>>(poses, views);
    finish_kernel<<<1, 1024>>>((float*)d_out);
}

// round 3
// speedup vs baseline: 1.2326x; 1.0231x over previous
#include <cuda_runtime.h>

#define S 160
#define SS (S*S)
#define S3 (S*S*S)
#define DG 96
#define DG2 (DG*DG)
#define DG3 (DG*DG*DG)
#define IMG_H 240
#define IMG_W 320
#define NVIEW 3
#define NSTEP 64
#define CLAMP_HI 158.999f          // f32(160 - 1.001)
#define NBLK 900                   // march blocks (10 x 30 x 3)

// packed resized SDF: g_sdf4[(x*S+y)*S+z] = (S[y][z], S[y][z+1], S[y+1][z], S[y+1][z+1])
__device__ float4 g_sdf4[S3];      // 64 MB, L2-resident
__device__ float  g_psum[NBLK];
__device__ int    g_pcnt[NBLK];
__device__ int    g_count;         // zero-initialized; reset after use

// ---------------------------------------------------------------------------
// Kernel 1: separable SDF resize 96^3 -> 160^3 (minus TRUNC), packed float4.
// One block per output (i,j). Computes rows j and j+1, packs (y,z) 2x2.
// ---------------------------------------------------------------------------
__global__ __launch_bounds__(160) void resize_sdf_kernel(const float* __restrict__ sdf) {
    int b = blockIdx.x;            // S*S
    int i = b / S, j = b % S;
    int j2 = min(j + 1, S - 1);
    int t = threadIdx.x;           // 160

    float cx = (i * 95.0f) / 159.0f;
    int x0 = (int)cx; float fx = cx - (float)x0; int x1 = min(x0 + 1, DG - 1);

    __shared__ float ls0[96], ls1[96];
    __shared__ float rA[161], rB[161];

    if (t < 96) {
        int xs = (x1 - x0) * DG2;
        float gxf = 1.0f - fx;
        {
            float cy = (j * 95.0f) / 159.0f;
            int y0 = (int)cy; float fy = cy - (float)y0; int y1 = min(y0 + 1, DG - 1);
            int base = (x0 * DG + y0) * DG + t;
            int ys = (y1 - y0) * DG;
            float gyf = 1.0f - fy;
            ls0[t] = __ldg(sdf + base) * (gxf * gyf) + __ldg(sdf + base + ys) * (gxf * fy)
                   + __ldg(sdf + base + xs) * (fx * gyf) + __ldg(sdf + base + xs + ys) * (fx * fy);
        }
        {
            float cy = (j2 * 95.0f) / 159.0f;
            int y0 = (int)cy; float fy = cy - (float)y0; int y1 = min(y0 + 1, DG - 1);
            int base = (x0 * DG + y0) * DG + t;
            int ys = (y1 - y0) * DG;
            float gyf = 1.0f - fy;
            ls1[t] = __ldg(sdf + base) * (gxf * gyf) + __ldg(sdf + base + ys) * (gxf * fy)
                   + __ldg(sdf + base + xs) * (fx * gyf) + __ldg(sdf + base + xs + ys) * (fx * fy);
        }
    }
    __syncthreads();

    float czf = (t * 95.0f) / 159.0f;
    int z0 = (int)czf; float fz = czf - (float)z0; int z1 = min(z0 + 1, DG - 1);

    float vA = fmaf(fz, ls0[z1] - ls0[z0], ls0[z0]) - 1.5f;
    float vB = fmaf(fz, ls1[z1] - ls1[z0], ls1[z0]) - 1.5f;
    rA[t] = vA; rB[t] = vB;
    if (t == 159) { rA[160] = vA; rB[160] = vB; }   // padding; never read by march
    __syncthreads();

    int o = (i * S + j) * S + t;
    g_sdf4[o] = make_float4(rA[t], rA[t + 1], rB[t], rB[t + 1]);
}

// ---------------------------------------------------------------------------
// SDF sample: 2 float4 loads (x0, x1 planes), nested lerp
// ---------------------------------------------------------------------------
__device__ __forceinline__ float sdf_sample4(float px, float py, float pz) {
    float cx = fminf(fmaxf(px, 0.0f), CLAMP_HI);
    float cy = fminf(fmaxf(py, 0.0f), CLAMP_HI);
    float cz = fminf(fmaxf(pz, 0.0f), CLAMP_HI);
    int x0 = (int)cx, y0 = (int)cy, z0 = (int)cz;
    float fx = cx - (float)x0, fy = cy - (float)y0, fz = cz - (float)z0;

    const float4* p = g_sdf4 + ((x0 * S + y0) * S + z0);
    float4 a = __ldg(p);
    float4 b = __ldg(p + SS);
    float a0 = fmaf(fz, a.y - a.x, a.x);
    float a1 = fmaf(fz, a.w - a.z, a.z);
    float b0 = fmaf(fz, b.y - b.x, b.x);
    float b1 = fmaf(fz, b.w - b.z, b.z);
    float va = fmaf(fy, a1 - a0, a0);
    float vb = fmaf(fy, b1 - b0, b0);
    return fmaf(fx, vb - va, va);
}

// 3-level separable weights for resized-trilerp-of-source-trilerp along one axis
__device__ __forceinline__ void axis_w(int c0, float f, float* W, int* g) {
    float cc0 = (c0 * 95.0f) / 159.0f;
    int b0 = (int)cc0; float f0 = cc0 - (float)b0;
    float cc1 = ((c0 + 1) * 95.0f) / 159.0f;
    int b1 = (int)cc1; float f1 = cc1 - (float)b1;
    int l = b1 - b0;                    // 0 or 1
    float g0 = 1.0f - f;
    float wa = f * (1.0f - f1), wb = f * f1;
    W[0] = g0 * (1.0f - f0) + (l == 0 ? wa : 0.0f);
    W[1] = g0 * f0 + (l == 0 ? wb : wa);
    W[2] = (l == 0 ? 0.0f : wb);
    g[0] = b0;
    g[1] = min(b0 + 1, DG - 1);
    g[2] = min(b0 + 2, DG - 1);
}

// ---------------------------------------------------------------------------
// Kernel 2: ray march + on-the-fly color/sem + full loss (last block finishes)
// grid (10, 30, 3), block 256 => 32w x 8h pixels per block, 8x4 warp tiles
// ---------------------------------------------------------------------------
__global__ __launch_bounds__(256) void march_kernel(
        const float* __restrict__ rgb,
        const float* __restrict__ sem,
        const float* __restrict__ poses,
        const float* __restrict__ views,
        float* __restrict__ out) {
    int tid = threadIdx.x;
    int warp = tid >> 5, lane = tid & 31;
    int wx = warp & 3, wy = warp >> 2;
    int lx = lane & 7, ly = lane >> 3;
    int w = blockIdx.x * 32 + wx * 8 + lx;
    int h = blockIdx.y * 8 + wy * 4 + ly;
    int v = blockIdx.z;

    const float offx[3] = {0.0f, 36.0f, 40.0f};
    const float offz[3] = {0.0f, 44.0f, 23.0f};

    const float* M = poses + v * 16;
    float ox = M[3]  / 0.0301f + offx[v];
    float oy = M[7]  / 0.0301f;
    float oz = M[11] / 0.0301f + offz[v];

    float uu = ((float)w - 160.0f) / 277.0f;
    float vv = ((float)h - 120.0f) / 277.0f;

    float dx = M[0] * uu + M[1] * vv + M[2];
    float dy = M[4] * uu + M[5] * vv + M[6];
    float dz = M[8] * uu + M[9] * vv + M[10];
    float nrm = sqrtf(dx * dx + dy * dy + dz * dz);
    dx /= nrm; dy /= nrm; dz /= nrm;

    float t = 0.0f;
    bool alive = true;
#pragma unroll 1
    for (int it = 0; it < NSTEP; ++it) {
        if (alive) {
            float px = fmaf(t, dx, ox);
            float py = fmaf(t, dy, oy);
            float pz = fmaf(t, dz, oz);
            bool dead = (px < 0.0f && dx <= 0.0f) || (px > 159.0f && dx >= 0.0f)
                     || (py < 0.0f && dy <= 0.0f) || (py > 159.0f && dy >= 0.0f)
                     || (pz < 0.0f && dz <= 0.0f) || (pz > 159.0f && dz >= 0.0f);
            if (dead) {
                alive = false;
            } else {
                float s = sdf_sample4(px, py, pz);
                t = fmaf(fmaxf(s, 0.25f), 2.0f, t);
            }
        }
        if (__all_sync(0xffffffffu, !alive)) break;
    }

    float contrib = 0.0f;
    int cnt = 0;
    if (alive) {
        float px = fmaf(t, dx, ox);
        float py = fmaf(t, dy, oy);
        float pz = fmaf(t, dz, oz);

        float cx = fminf(fmaxf(px, 0.0f), CLAMP_HI);
        float cy = fminf(fmaxf(py, 0.0f), CLAMP_HI);
        float cz = fminf(fmaxf(pz, 0.0f), CLAMP_HI);
        int x0 = (int)cx, y0 = (int)cy, z0 = (int)cz;
        float fx = cx - (float)x0, fy = cy - (float)y0, fz = cz - (float)z0;

        const float4* p = g_sdf4 + ((x0 * S + y0) * S + z0);
        float4 a = __ldg(p);
        float4 bq = __ldg(p + SS);
        float a0 = fmaf(fz, a.y - a.x, a.x);
        float a1 = fmaf(fz, a.w - a.z, a.z);
        float b0 = fmaf(fz, bq.y - bq.x, bq.x);
        float b1 = fmaf(fz, bq.w - bq.z, bq.z);
        float va = fmaf(fy, a1 - a0, a0);
        float vb = fmaf(fy, b1 - b0, b0);
        float s = fmaf(fx, vb - va, va);

        bool inside = (px >= 0.0f) && (px <= 159.0f)
                   && (py >= 0.0f) && (py <= 159.0f)
                   && (pz >= 0.0f) && (pz <= 159.0f);
        bool valid = inside && (fabsf(s) < 1.0f);

        if (valid) {
            // separable 3x3x3 color gather
            float Wx[3], Wy[3], Wz[3];
            int gx[3], gy[3], gz[3];
            axis_w(x0, fx, Wx, gx);
            axis_w(y0, fy, Wy, gy);
            axis_w(z0, fz, Wz, gz);

            float col[3];
#pragma unroll
            for (int c = 0; c < 3; c++) {
                const float* src = rgb + c * DG3;
                float acc = 0.0f;
#pragma unroll
                for (int ia = 0; ia < 3; ia++) {
                    float accy = 0.0f;
#pragma unroll
                    for (int ib = 0; ib < 3; ib++) {
                        const float* r = src + (gx[ia] * DG + gy[ib]) * DG;
                        float accz = __ldg(r + gz[0]) * Wz[0]
                                   + __ldg(r + gz[1]) * Wz[1]
                                   + __ldg(r + gz[2]) * Wz[2];
                        accy = fmaf(Wy[ib], accz, accy);
                    }
                    acc = fmaf(Wx[ia], accy, acc);
                }
                col[c] = acc;
            }

            // sem: trilerp of NN-resized volume = 2x2x2 gather with NN indices
            int nx0 = min((int)(x0 * 0.6f), DG - 1);
            int nx1 = min((int)((x0 + 1) * 0.6f), DG - 1);
            int ny0 = min((int)(y0 * 0.6f), DG - 1);
            int ny1 = min((int)((y0 + 1) * 0.6f), DG - 1);
            int nz0 = min((int)(z0 * 0.6f), DG - 1);
            int nz1 = min((int)((z0 + 1) * 0.6f), DG - 1);
            float gxf = 1.0f - fx, gyf = 1.0f - fy, gzf = 1.0f - fz;
            const float* s00 = sem + (nx0 * DG + ny0) * DG;
            const float* s01 = sem + (nx0 * DG + ny1) * DG;
            const float* s10 = sem + (nx1 * DG + ny0) * DG;
            const float* s11 = sem + (nx1 * DG + ny1) * DG;
            float wv = gxf * gyf * (gzf * __ldg(s00 + nz0) + fz * __ldg(s00 + nz1))
                     + gxf * fy  * (gzf * __ldg(s01 + nz0) + fz * __ldg(s01 + nz1))
                     + fx  * gyf * (gzf * __ldg(s10 + nz0) + fz * __ldg(s10 + nz1))
                     + fx  * fy  * (gzf * __ldg(s11 + nz0) + fz * __ldg(s11 + nz1));

            const float* vw = views + ((size_t)(v * IMG_H + h) * IMG_W + w) * 3;
            contrib = (fabsf(col[0] - vw[0]) + fabsf(col[1] - vw[1])
                     + fabsf(col[2] - vw[2])) * wv;
            cnt = 1;
        }
    }

    // deterministic block reduction
    __shared__ float ssum[256];
    __shared__ int scnt[256];
    ssum[tid] = contrib;
    scnt[tid] = cnt;
    __syncthreads();
#pragma unroll
    for (int o = 128; o > 0; o >>= 1) {
        if (tid < o) {
            ssum[tid] += ssum[tid + o];
            scnt[tid] += scnt[tid + o];
        }
        __syncthreads();
    }
    int bid = (blockIdx.z * gridDim.y + blockIdx.y) * gridDim.x + blockIdx.x;
    __shared__ bool amLast;
    if (tid == 0) {
        g_psum[bid] = ssum[0];
        g_pcnt[bid] = scnt[0];
        __threadfence();
        int tk = atomicAdd(&g_count, 1);
        amLast = (tk == NBLK - 1);
    }
    __syncthreads();

    if (amLast) {
        float sacc = 0.0f; int cacc = 0;
        for (int k = tid; k < NBLK; k += 256) {
            sacc += g_psum[k];
            cacc += g_pcnt[k];
        }
        ssum[tid] = sacc;
        scnt[tid] = cacc;
        __syncthreads();
#pragma unroll
        for (int o = 128; o > 0; o >>= 1) {
            if (tid < o) {
                ssum[tid] += ssum[tid + o];
                scnt[tid] += scnt[tid + o];
            }
            __syncthreads();
        }
        if (tid == 0) {
            float nv = 3.0f * (float)scnt[0];
            out[0] = 8.0f * ssum[0] / fmaxf(nv, 1.0f);
            g_count = 0;               // reset for next graph replay
        }
    }
}

// ---------------------------------------------------------------------------
extern "C" void kernel_launch(void* const* d_in, const int* in_sizes, int n_in,
                              void* d_out, int out_size) {
    const float* sdf   = (const float*)d_in[0];
    const float* rgb   = (const float*)d_in[1];
    const float* sem   = (const float*)d_in[2];
    const float* poses = (const float*)d_in[3];
    const float* views = (const float*)d_in[4];

    resize_sdf_kernel<<<S * S, 160>>>(sdf);
    dim3 mg(IMG_W / 32, IMG_H / 8, NVIEW);
    march_kernel<<<mg, 256>>>(rgb, sem, poses, views, (float*)d_out);
}